// round 4
// baseline (speedup 1.0000x reference)
#include <cuda_runtime.h>
#include <cstdint>

// -------------------------------------------------------------------------
// SpecialSpmmFinal: out[n, f] = sum over edges e with edge[0][e]==n of
// edge_w[e, f].   N=100000, E=3200000, F=16 (fp32).
//
// Inputs (metadata order):
//   d_in[0] : edge    int32 [2, E]   (row 0 = src indices, contiguous)
//   d_in[1] : edge_w  fp32  [E, 16]
//   d_in[2..] : scalars N, E, out_features
// Output: fp32 [N, 16]
//
// Strategy: one thread per edge; 4x float4 coalesced loads of the 64-byte
// edge_w row; 4x red.global.add.v4.f32 into the 64-byte output row.
// -------------------------------------------------------------------------

#define FEAT 16

__global__ __launch_bounds__(256)
void zero_out_kernel(float4* __restrict__ out, int n4) {
    int i = blockIdx.x * blockDim.x + threadIdx.x;
    if (i < n4) out[i] = make_float4(0.f, 0.f, 0.f, 0.f);
}

__global__ __launch_bounds__(256)
void spmm_scatter_kernel(const int* __restrict__ src,
                         const float4* __restrict__ w,   // [E*4] float4
                         float* __restrict__ out,        // [N*16]
                         int E) {
    int e = blockIdx.x * blockDim.x + threadIdx.x;
    if (e >= E) return;

    int s = src[e];

    const float4* wr = w + (size_t)e * 4;
    float4 a = wr[0];
    float4 b = wr[1];
    float4 c = wr[2];
    float4 d = wr[3];

    float* o = out + (size_t)s * FEAT;

    asm volatile("red.global.add.v4.f32 [%0], {%1,%2,%3,%4};"
                 :: "l"(o + 0), "f"(a.x), "f"(a.y), "f"(a.z), "f"(a.w) : "memory");
    asm volatile("red.global.add.v4.f32 [%0], {%1,%2,%3,%4};"
                 :: "l"(o + 4), "f"(b.x), "f"(b.y), "f"(b.z), "f"(b.w) : "memory");
    asm volatile("red.global.add.v4.f32 [%0], {%1,%2,%3,%4};"
                 :: "l"(o + 8), "f"(c.x), "f"(c.y), "f"(c.z), "f"(c.w) : "memory");
    asm volatile("red.global.add.v4.f32 [%0], {%1,%2,%3,%4};"
                 :: "l"(o + 12), "f"(d.x), "f"(d.y), "f"(d.z), "f"(d.w) : "memory");
}

extern "C" void kernel_launch(void* const* d_in, const int* in_sizes, int n_in,
                              void* d_out, int out_size) {
    const int*    edge   = (const int*)d_in[0];      // [2, E], row 0 = src
    const float4* edge_w = (const float4*)d_in[1];   // [E, 16] fp32 as float4
    float*        out    = (float*)d_out;            // [N, 16] fp32

    const int E = in_sizes[0] / 2;

    // Zero the (poisoned) output: out_size floats, always a multiple of 4.
    {
        int n4 = out_size / 4;
        int blocks = (n4 + 255) / 256;
        zero_out_kernel<<<blocks, 256>>>((float4*)out, n4);
    }

    // Scatter-accumulate (stream-ordered after the zero kernel).
    {
        int blocks = (E + 255) / 256;
        spmm_scatter_kernel<<<blocks, 256>>>(edge, edge_w, out, E);
    }
}